// round 1
// baseline (speedup 1.0000x reference)
#include <cuda_runtime.h>
#include <cstdint>

#define D_MODEL 2048
#define KV_DIM  512
#define NHEADS  32
#define NKVH    8
#define HD      64
#define SEQ     1024
#define BATCH   4
#define MTOT    (BATCH * SEQ)   // 4096

// ---------------- scratch (no cudaMalloc allowed) ----------------
__device__ float g_q[MTOT * D_MODEL];   // 33.5 MB
__device__ float g_k[MTOT * KV_DIM];    //  8.4 MB
__device__ float g_v[MTOT * KV_DIM];    //  8.4 MB
__device__ float g_ctx[MTOT * D_MODEL]; // 33.5 MB

// =================================================================
// SGEMM: C[M,N] = A[M,K] @ B[K,N] + bias[N]
// 128x128 tile, BK=16, 256 threads, 8x8 per thread.
// A staged transposed in smem (k-major) so compute reads are float4.
// =================================================================
__global__ __launch_bounds__(256) void sgemm_bias_kernel(
    const float* __restrict__ A, const float* __restrict__ B,
    const float* __restrict__ bias, float* __restrict__ C,
    int M, int N, int K)
{
    __shared__ float As[16][128];
    __shared__ float Bs[16][128];

    const int tid = threadIdx.x;
    const int tx = tid & 15;          // 0..15  -> 8 cols each
    const int ty = tid >> 4;          // 0..15  -> 8 rows each
    const int crow = blockIdx.y * 128;
    const int ccol = blockIdx.x * 128;

    // A-load mapping: each thread loads 2x float4 of one row segment
    const int ar  = tid >> 1;                  // 0..127
    const int ac0 = (tid & 1) * 8;             // 0 or 8
    // B-load mapping: rows br, br+8 ; 4 consecutive floats
    const int bcol = (tid & 31) * 4;
    const int br   = tid >> 5;                 // 0..7

    const float* Aptr = A + (size_t)(crow + ar) * K + ac0;
    const float* Bptr = B + (size_t)br * N + ccol + bcol;

    float acc[8][8];
    #pragma unroll
    for (int i = 0; i < 8; i++)
        #pragma unroll
        for (int j = 0; j < 8; j++) acc[i][j] = 0.f;

    for (int k0 = 0; k0 < K; k0 += 16) {
        float4 a0 = *(const float4*)(Aptr + k0);
        float4 a1 = *(const float4*)(Aptr + k0 + 4);
        float4 b0 = *(const float4*)(Bptr + (size_t)k0 * N);
        float4 b1 = *(const float4*)(Bptr + (size_t)(k0 + 8) * N);
        __syncthreads();
        As[ac0 + 0][ar] = a0.x; As[ac0 + 1][ar] = a0.y;
        As[ac0 + 2][ar] = a0.z; As[ac0 + 3][ar] = a0.w;
        As[ac0 + 4][ar] = a1.x; As[ac0 + 5][ar] = a1.y;
        As[ac0 + 6][ar] = a1.z; As[ac0 + 7][ar] = a1.w;
        *(float4*)&Bs[br][bcol]     = b0;
        *(float4*)&Bs[br + 8][bcol] = b1;
        __syncthreads();
        #pragma unroll
        for (int kk = 0; kk < 16; kk++) {
            float a[8], b[8];
            *(float4*)&a[0] = *(const float4*)&As[kk][ty * 8];
            *(float4*)&a[4] = *(const float4*)&As[kk][ty * 8 + 4];
            *(float4*)&b[0] = *(const float4*)&Bs[kk][tx * 8];
            *(float4*)&b[4] = *(const float4*)&Bs[kk][tx * 8 + 4];
            #pragma unroll
            for (int i = 0; i < 8; i++)
                #pragma unroll
                for (int j = 0; j < 8; j++)
                    acc[i][j] += a[i] * b[j];
        }
    }

    // epilogue: bias add + store
    #pragma unroll
    for (int i = 0; i < 8; i++) {
        const int row = crow + ty * 8 + i;
        float* cp = C + (size_t)row * N + ccol + tx * 8;
        const float* bp = bias + ccol + tx * 8;
        #pragma unroll
        for (int j = 0; j < 8; j++)
            cp[j] = acc[i][j] + bp[j];
    }
}

// =================================================================
// Flash attention (fp32): one block per (b, h, 128-query tile).
// Q and K staged transposed (k-major) in smem; streaming softmax;
// P staged through smem for the AV GEMM.
// Thread layout: ty=tid/16 owns 8 q-rows; tx=tid%16 owns 8 key-cols
// in the S GEMM and 4 d-cols in the AV GEMM.
// =================================================================
#define QTS_PITCH 132          // [64][132]
#define KTS_PITCH 132          // [64][132]
#define PS_PITCH  132          // [128][132]
#define SM_QTS   0
#define SM_KTS   (SM_QTS + 64 * QTS_PITCH)
#define SM_VS    (SM_KTS + 64 * KTS_PITCH)
#define SM_PS    (SM_VS + 128 * 64)
#define ATTN_SMEM_FLOATS (SM_PS + 128 * PS_PITCH)
#define ATTN_SMEM_BYTES  (ATTN_SMEM_FLOATS * 4)   // 167936 B

__global__ __launch_bounds__(256, 1) void attn_kernel(
    const float* __restrict__ q, const float* __restrict__ k,
    const float* __restrict__ v, float* __restrict__ ctx)
{
    extern __shared__ float sm[];
    float* Qts = sm + SM_QTS;   // [64 d][132]   (k-major Q tile)
    float* Kts = sm + SM_KTS;   // [64 d][132]   (k-major K tile)
    float* Vs  = sm + SM_VS;    // [128 key][64]
    float* Ps  = sm + SM_PS;    // [128 row][132]

    const int tid = threadIdx.x;
    const int tx = tid & 15;
    const int ty = tid >> 4;
    const int qt = blockIdx.x;       // 0..7
    const int h  = blockIdx.y;       // 0..31
    const int b  = blockIdx.z;       // 0..3
    const int kvh = h >> 2;          // 4 query heads per kv head

    const int qrow0 = b * SEQ + qt * 128;
    const float* qbase = q + (size_t)qrow0 * D_MODEL + h * HD;
    const float* kbase = k + (size_t)b * SEQ * KV_DIM + kvh * HD;
    const float* vbase = v + (size_t)b * SEQ * KV_DIM + kvh * HD;

    // ---- load Q tile transposed: Qts[d][row] ----
    {
        const int r  = tid >> 1;
        const int c0 = (tid & 1) * 32;
        const float* src = qbase + (size_t)r * D_MODEL + c0;
        #pragma unroll
        for (int i = 0; i < 8; i++) {
            float4 v4 = *(const float4*)(src + i * 4);
            Qts[(c0 + i * 4 + 0) * QTS_PITCH + r] = v4.x;
            Qts[(c0 + i * 4 + 1) * QTS_PITCH + r] = v4.y;
            Qts[(c0 + i * 4 + 2) * QTS_PITCH + r] = v4.z;
            Qts[(c0 + i * 4 + 3) * QTS_PITCH + r] = v4.w;
        }
    }

    float m[8], l[8], o[8][4];
    #pragma unroll
    for (int i = 0; i < 8; i++) {
        m[i] = -1e30f; l[i] = 0.f;
        #pragma unroll
        for (int j = 0; j < 4; j++) o[i][j] = 0.f;
    }

    for (int kt = 0; kt < SEQ; kt += 128) {
        __syncthreads();   // prev AV reads (and Q-load on first iter) done
        // ---- load K tile transposed + V tile ----
        {
            const int key = tid >> 1;
            const int c0  = (tid & 1) * 32;
            const float* ksrc = kbase + (size_t)(kt + key) * KV_DIM + c0;
            const float* vsrc = vbase + (size_t)(kt + key) * KV_DIM + c0;
            #pragma unroll
            for (int i = 0; i < 8; i++) {
                float4 k4 = *(const float4*)(ksrc + i * 4);
                Kts[(c0 + i * 4 + 0) * KTS_PITCH + key] = k4.x;
                Kts[(c0 + i * 4 + 1) * KTS_PITCH + key] = k4.y;
                Kts[(c0 + i * 4 + 2) * KTS_PITCH + key] = k4.z;
                Kts[(c0 + i * 4 + 3) * KTS_PITCH + key] = k4.w;
                *(float4*)&Vs[key * 64 + c0 + i * 4] = *(const float4*)(vsrc + i * 4);
            }
        }
        __syncthreads();

        // ---- S = (Q K^T) * 0.125 : 8x8 micro-tile per thread ----
        float s[8][8];
        #pragma unroll
        for (int i = 0; i < 8; i++)
            #pragma unroll
            for (int j = 0; j < 8; j++) s[i][j] = 0.f;

        #pragma unroll 8
        for (int kk = 0; kk < 64; kk++) {
            float a[8], bb[8];
            *(float4*)&a[0]  = *(const float4*)&Qts[kk * QTS_PITCH + ty * 8];
            *(float4*)&a[4]  = *(const float4*)&Qts[kk * QTS_PITCH + ty * 8 + 4];
            *(float4*)&bb[0] = *(const float4*)&Kts[kk * KTS_PITCH + tx * 8];
            *(float4*)&bb[4] = *(const float4*)&Kts[kk * KTS_PITCH + tx * 8 + 4];
            #pragma unroll
            for (int i = 0; i < 8; i++)
                #pragma unroll
                for (int j = 0; j < 8; j++)
                    s[i][j] += a[i] * bb[j];
        }

        // ---- streaming softmax update (row groups of 16 tx lanes) ----
        #pragma unroll
        for (int i = 0; i < 8; i++) {
            float mx = -1e30f;
            #pragma unroll
            for (int j = 0; j < 8; j++) {
                s[i][j] *= 0.125f;
                mx = fmaxf(mx, s[i][j]);
            }
            #pragma unroll
            for (int off = 8; off >= 1; off >>= 1)
                mx = fmaxf(mx, __shfl_xor_sync(0xffffffffu, mx, off));
            const float mn = fmaxf(m[i], mx);
            const float corr = __expf(m[i] - mn);
            m[i] = mn;
            float rs = 0.f;
            #pragma unroll
            for (int j = 0; j < 8; j++) {
                const float p = __expf(s[i][j] - mn);
                s[i][j] = p;
                rs += p;
            }
            #pragma unroll
            for (int off = 8; off >= 1; off >>= 1)
                rs += __shfl_xor_sync(0xffffffffu, rs, off);
            l[i] = l[i] * corr + rs;
            #pragma unroll
            for (int j = 0; j < 4; j++) o[i][j] *= corr;
        }

        // ---- stage P in smem ----
        #pragma unroll
        for (int i = 0; i < 8; i++) {
            float* pp = &Ps[(ty * 8 + i) * PS_PITCH + tx * 8];
            *(float4*)&pp[0] = make_float4(s[i][0], s[i][1], s[i][2], s[i][3]);
            *(float4*)&pp[4] = make_float4(s[i][4], s[i][5], s[i][6], s[i][7]);
        }
        __syncthreads();

        // ---- O += P @ V : 8 rows x 4 d-cols per thread ----
        #pragma unroll 4
        for (int kk = 0; kk < 128; kk++) {
            float bb[4];
            *(float4*)&bb[0] = *(const float4*)&Vs[kk * 64 + tx * 4];
            #pragma unroll
            for (int i = 0; i < 8; i++) {
                const float a = Ps[(ty * 8 + i) * PS_PITCH + kk];
                #pragma unroll
                for (int j = 0; j < 4; j++)
                    o[i][j] += a * bb[j];
            }
        }
    }

    // ---- epilogue: normalize and write ctx in [B,S,D] layout ----
    #pragma unroll
    for (int i = 0; i < 8; i++) {
        const float inv = 1.0f / l[i];
        const int row = qrow0 + ty * 8 + i;
        float* cp = ctx + (size_t)row * D_MODEL + h * HD + tx * 4;
        #pragma unroll
        for (int j = 0; j < 4; j++)
            cp[j] = o[i][j] * inv;
    }
}

// =================================================================
extern "C" void kernel_launch(void* const* d_in, const int* in_sizes, int n_in,
                              void* d_out, int out_size)
{
    const float* x  = (const float*)d_in[0];
    const float* Wq = (const float*)d_in[1];
    const float* bq = (const float*)d_in[2];
    const float* Wk = (const float*)d_in[3];
    const float* bk = (const float*)d_in[4];
    const float* Wv = (const float*)d_in[5];
    const float* bv = (const float*)d_in[6];
    const float* Wo = (const float*)d_in[7];
    const float* bo = (const float*)d_in[8];
    float* out = (float*)d_out;

    float *qp, *kp, *vp, *cp;
    cudaGetSymbolAddress((void**)&qp, g_q);
    cudaGetSymbolAddress((void**)&kp, g_k);
    cudaGetSymbolAddress((void**)&vp, g_v);
    cudaGetSymbolAddress((void**)&cp, g_ctx);

    cudaFuncSetAttribute(attn_kernel,
                         cudaFuncAttributeMaxDynamicSharedMemorySize,
                         ATTN_SMEM_BYTES);

    dim3 blk(256);
    // Q/K/V projections
    sgemm_bias_kernel<<<dim3(D_MODEL / 128, MTOT / 128), blk>>>(x, Wq, bq, qp, MTOT, D_MODEL, D_MODEL);
    sgemm_bias_kernel<<<dim3(KV_DIM  / 128, MTOT / 128), blk>>>(x, Wk, bk, kp, MTOT, KV_DIM,  D_MODEL);
    sgemm_bias_kernel<<<dim3(KV_DIM  / 128, MTOT / 128), blk>>>(x, Wv, bv, vp, MTOT, KV_DIM,  D_MODEL);
    // attention
    attn_kernel<<<dim3(SEQ / 128, NHEADS, BATCH), blk, ATTN_SMEM_BYTES>>>(qp, kp, vp, cp);
    // output projection
    sgemm_bias_kernel<<<dim3(D_MODEL / 128, MTOT / 128), blk>>>(cp, Wo, bo, out, MTOT, D_MODEL, D_MODEL);
}

// round 3
// speedup vs baseline: 1.4993x; 1.4993x over previous
#include <cuda_runtime.h>
#include <cstdint>

#define D_MODEL 2048
#define KV_DIM  512
#define NHEADS  32
#define NKVH    8
#define HD      64
#define SEQ     1024
#define BATCH   4
#define MTOT    (BATCH * SEQ)   // 4096

// ---------------- scratch (no cudaMalloc allowed) ----------------
__device__ __align__(256) float g_q[MTOT * D_MODEL];
__device__ __align__(256) float g_k[MTOT * KV_DIM];
__device__ __align__(256) float g_v[MTOT * KV_DIM];
__device__ __align__(256) float g_ctx[MTOT * D_MODEL];
__device__ __align__(256) float g_xr[MTOT * D_MODEL];     // tf32-rounded x
__device__ __align__(256) float g_wt[D_MODEL * D_MODEL];  // transposed+rounded weight (reused)

// ================= helpers =================
__device__ __forceinline__ uint32_t smem_u32(const void* p) {
    uint32_t a;
    asm("{ .reg .u64 t; cvta.to.shared.u64 t, %1; cvt.u32.u64 %0, t; }" : "=r"(a) : "l"(p));
    return a;
}
__device__ __forceinline__ float tf32r(float x) {
    float y;
    asm("cvt.rna.tf32.f32 %0, %1;" : "=f"(y) : "f"(x));
    return y;
}

// ================= prep kernels =================
__global__ void round_copy_kernel(const float4* __restrict__ in, float4* __restrict__ out, int n4) {
    int i = blockIdx.x * blockDim.x + threadIdx.x;
    if (i < n4) {
        float4 v = in[i];
        v.x = tf32r(v.x); v.y = tf32r(v.y); v.z = tf32r(v.z); v.w = tf32r(v.w);
        out[i] = v;
    }
}

// W [K, N] row-major -> Wt [N, K] row-major, tf32-rounded
__global__ void transpose_round_kernel(const float* __restrict__ W, float* __restrict__ Wt,
                                       int K, int N) {
    __shared__ float t[32][33];
    const int n0 = blockIdx.x * 32, k0 = blockIdx.y * 32;
    const int tx = threadIdx.x, ty = threadIdx.y;  // 32 x 8
    #pragma unroll
    for (int i = 0; i < 32; i += 8)
        t[ty + i][tx] = W[(size_t)(k0 + ty + i) * N + n0 + tx];
    __syncthreads();
    #pragma unroll
    for (int i = 0; i < 32; i += 8)
        Wt[(size_t)(n0 + ty + i) * K + k0 + tx] = tf32r(t[tx][ty + i]);
}

// ================= warp-MMA tf32 GEMM =================
// C[M,N] = A[M,K] @ Bt[N,K]^T + bias.  A, Bt pre-rounded to tf32.
// 128x128 tile, BK=32, 256 threads = 8 warps (2 x 4 -> 64x32 per warp).
// 3-stage cp.async pipeline. Smem pitch 36 floats: frag LDS bank == lane
// (conflict-free) and rows are 16B-aligned (144 B pitch).
#define GS   3
#define GP   36
#define GA_STAGE      (128 * GP)              // floats per A tile
#define GSTAGE_FLOATS (2 * 128 * GP)          // A + B
#define GEMM_SMEM     (GS * GSTAGE_FLOATS * 4)  // 110592 B

__device__ __forceinline__ void mma_tf32(float c[4], uint32_t a0, uint32_t a1,
                                         uint32_t a2, uint32_t a3,
                                         uint32_t b0, uint32_t b1) {
    asm volatile(
        "mma.sync.aligned.m16n8k8.row.col.f32.tf32.tf32.f32 "
        "{%0,%1,%2,%3}, {%4,%5,%6,%7}, {%8,%9}, {%0,%1,%2,%3};"
        : "+f"(c[0]), "+f"(c[1]), "+f"(c[2]), "+f"(c[3])
        : "r"(a0), "r"(a1), "r"(a2), "r"(a3), "r"(b0), "r"(b1));
}

__global__ __launch_bounds__(256, 1) void gemm_mma_kernel(
    const float* __restrict__ A, const float* __restrict__ Bt,
    const float* __restrict__ bias, float* __restrict__ C,
    int M, int N, int K)
{
    extern __shared__ __align__(16) float gsm[];

    const int tid  = threadIdx.x;
    const int wid  = tid >> 5;
    const int lane = tid & 31;
    const int m0 = blockIdx.y * 128;
    const int n0 = blockIdx.x * 128;
    const int wm = wid & 1;    // 0..1 -> 64 rows
    const int wn = wid >> 1;   // 0..3 -> 32 cols

    // ---- staging mapping: threads 0..127 -> A rows, 128..255 -> Bt rows ----
    const bool isA = tid < 128;
    const int  row = isA ? tid : tid - 128;
    const float* gsrc = isA ? (A + (size_t)(m0 + row) * K)
                            : (Bt + (size_t)(n0 + row) * K);
    const uint32_t sdst_row = smem_u32(gsm) +
        ((isA ? 0 : GA_STAGE) + row * GP) * 4;

    const int nChunks = K / 32;

    // issue one stage: thread copies its row's 32 floats (8 x 16B, contiguous gmem)
    #define GISSUE(ch, st) do {                                                \
        uint32_t _d = sdst_row + (st) * (GSTAGE_FLOATS * 4);                   \
        const float* _g = gsrc + (ch) * 32;                                    \
        _Pragma("unroll")                                                      \
        for (int _c = 0; _c < 8; _c++)                                         \
            asm volatile("cp.async.cg.shared.global [%0], [%1], 16;"           \
                         :: "r"(_d + _c * 16), "l"(_g + _c * 4) : "memory");   \
    } while (0)

    GISSUE(0, 0);
    asm volatile("cp.async.commit_group;" ::: "memory");
    GISSUE(1, 1);
    asm volatile("cp.async.commit_group;" ::: "memory");

    float acc[4][4][4];
    #pragma unroll
    for (int mi = 0; mi < 4; mi++)
        #pragma unroll
        for (int ni = 0; ni < 4; ni++)
            #pragma unroll
            for (int r = 0; r < 4; r++) acc[mi][ni][r] = 0.f;

    const int frow = lane >> 2;   // 0..7
    const int fcol = lane & 3;    // 0..3

    for (int ch = 0; ch < nChunks; ch++) {
        asm volatile("cp.async.wait_group 1;" ::: "memory");
        __syncthreads();
        if (ch + 2 < nChunks) GISSUE(ch + 2, (ch + 2) % GS);
        asm volatile("cp.async.commit_group;" ::: "memory");

        const float* As = gsm + (ch % GS) * GSTAGE_FLOATS;
        const float* Bs = As + GA_STAGE;

        #pragma unroll
        for (int ks = 0; ks < 4; ks++) {
            const int kb = ks * 8 + fcol;
            uint32_t a[4][4], b[4][2];
            #pragma unroll
            for (int mi = 0; mi < 4; mi++) {
                const float* p = As + (wm * 64 + mi * 16 + frow) * GP + kb;
                a[mi][0] = __float_as_uint(p[0]);
                a[mi][1] = __float_as_uint(p[8 * GP]);
                a[mi][2] = __float_as_uint(p[4]);
                a[mi][3] = __float_as_uint(p[8 * GP + 4]);
            }
            #pragma unroll
            for (int ni = 0; ni < 4; ni++) {
                const float* p = Bs + (wn * 32 + ni * 8 + frow) * GP + kb;
                b[ni][0] = __float_as_uint(p[0]);
                b[ni][1] = __float_as_uint(p[4]);
            }
            #pragma unroll
            for (int mi = 0; mi < 4; mi++)
                #pragma unroll
                for (int ni = 0; ni < 4; ni++)
                    mma_tf32(acc[mi][ni], a[mi][0], a[mi][1], a[mi][2], a[mi][3],
                             b[ni][0], b[ni][1]);
        }
    }
    #undef GISSUE

    // ---- epilogue: bias + store (float2 per fragment half) ----
    #pragma unroll
    for (int mi = 0; mi < 4; mi++) {
        const int r0 = m0 + wm * 64 + mi * 16 + frow;
        #pragma unroll
        for (int ni = 0; ni < 4; ni++) {
            const int col = n0 + wn * 32 + ni * 8 + 2 * fcol;
            const float b0 = bias[col], b1 = bias[col + 1];
            float2 v0 = make_float2(acc[mi][ni][0] + b0, acc[mi][ni][1] + b1);
            float2 v1 = make_float2(acc[mi][ni][2] + b0, acc[mi][ni][3] + b1);
            *(float2*)(C + (size_t)r0 * N + col) = v0;
            *(float2*)(C + (size_t)(r0 + 8) * N + col) = v1;
        }
    }
}

// =================================================================
// Flash attention (fp32) — unchanged; writes tf32-rounded ctx
// =================================================================
#define QTS_PITCH 132
#define KTS_PITCH 132
#define PS_PITCH  132
#define SM_QTS   0
#define SM_KTS   (SM_QTS + 64 * QTS_PITCH)
#define SM_VS    (SM_KTS + 64 * KTS_PITCH)
#define SM_PS    (SM_VS + 128 * 64)
#define ATTN_SMEM_FLOATS (SM_PS + 128 * PS_PITCH)
#define ATTN_SMEM_BYTES  (ATTN_SMEM_FLOATS * 4)

__global__ __launch_bounds__(256, 1) void attn_kernel(
    const float* __restrict__ q, const float* __restrict__ k,
    const float* __restrict__ v, float* __restrict__ ctx)
{
    extern __shared__ float sm[];
    float* Qts = sm + SM_QTS;
    float* Kts = sm + SM_KTS;
    float* Vs  = sm + SM_VS;
    float* Ps  = sm + SM_PS;

    const int tid = threadIdx.x;
    const int tx = tid & 15;
    const int ty = tid >> 4;
    const int qt = blockIdx.x;
    const int h  = blockIdx.y;
    const int b  = blockIdx.z;
    const int kvh = h >> 2;

    const int qrow0 = b * SEQ + qt * 128;
    const float* qbase = q + (size_t)qrow0 * D_MODEL + h * HD;
    const float* kbase = k + (size_t)b * SEQ * KV_DIM + kvh * HD;
    const float* vbase = v + (size_t)b * SEQ * KV_DIM + kvh * HD;

    {
        const int r  = tid >> 1;
        const int c0 = (tid & 1) * 32;
        const float* src = qbase + (size_t)r * D_MODEL + c0;
        #pragma unroll
        for (int i = 0; i < 8; i++) {
            float4 v4 = *(const float4*)(src + i * 4);
            Qts[(c0 + i * 4 + 0) * QTS_PITCH + r] = v4.x;
            Qts[(c0 + i * 4 + 1) * QTS_PITCH + r] = v4.y;
            Qts[(c0 + i * 4 + 2) * QTS_PITCH + r] = v4.z;
            Qts[(c0 + i * 4 + 3) * QTS_PITCH + r] = v4.w;
        }
    }

    float m[8], l[8], o[8][4];
    #pragma unroll
    for (int i = 0; i < 8; i++) {
        m[i] = -1e30f; l[i] = 0.f;
        #pragma unroll
        for (int j = 0; j < 4; j++) o[i][j] = 0.f;
    }

    for (int kt = 0; kt < SEQ; kt += 128) {
        __syncthreads();
        {
            const int key = tid >> 1;
            const int c0  = (tid & 1) * 32;
            const float* ksrc = kbase + (size_t)(kt + key) * KV_DIM + c0;
            const float* vsrc = vbase + (size_t)(kt + key) * KV_DIM + c0;
            #pragma unroll
            for (int i = 0; i < 8; i++) {
                float4 k4 = *(const float4*)(ksrc + i * 4);
                Kts[(c0 + i * 4 + 0) * KTS_PITCH + key] = k4.x;
                Kts[(c0 + i * 4 + 1) * KTS_PITCH + key] = k4.y;
                Kts[(c0 + i * 4 + 2) * KTS_PITCH + key] = k4.z;
                Kts[(c0 + i * 4 + 3) * KTS_PITCH + key] = k4.w;
                *(float4*)&Vs[key * 64 + c0 + i * 4] = *(const float4*)(vsrc + i * 4);
            }
        }
        __syncthreads();

        float s[8][8];
        #pragma unroll
        for (int i = 0; i < 8; i++)
            #pragma unroll
            for (int j = 0; j < 8; j++) s[i][j] = 0.f;

        #pragma unroll 8
        for (int kk = 0; kk < 64; kk++) {
            float a[8], bb[8];
            *(float4*)&a[0]  = *(const float4*)&Qts[kk * QTS_PITCH + ty * 8];
            *(float4*)&a[4]  = *(const float4*)&Qts[kk * QTS_PITCH + ty * 8 + 4];
            *(float4*)&bb[0] = *(const float4*)&Kts[kk * KTS_PITCH + tx * 8];
            *(float4*)&bb[4] = *(const float4*)&Kts[kk * KTS_PITCH + tx * 8 + 4];
            #pragma unroll
            for (int i = 0; i < 8; i++)
                #pragma unroll
                for (int j = 0; j < 8; j++)
                    s[i][j] += a[i] * bb[j];
        }

        #pragma unroll
        for (int i = 0; i < 8; i++) {
            float mx = -1e30f;
            #pragma unroll
            for (int j = 0; j < 8; j++) {
                s[i][j] *= 0.125f;
                mx = fmaxf(mx, s[i][j]);
            }
            #pragma unroll
            for (int off = 8; off >= 1; off >>= 1)
                mx = fmaxf(mx, __shfl_xor_sync(0xffffffffu, mx, off));
            const float mn = fmaxf(m[i], mx);
            const float corr = __expf(m[i] - mn);
            m[i] = mn;
            float rs = 0.f;
            #pragma unroll
            for (int j = 0; j < 8; j++) {
                const float p = __expf(s[i][j] - mn);
                s[i][j] = p;
                rs += p;
            }
            #pragma unroll
            for (int off = 8; off >= 1; off >>= 1)
                rs += __shfl_xor_sync(0xffffffffu, rs, off);
            l[i] = l[i] * corr + rs;
            #pragma unroll
            for (int j = 0; j < 4; j++) o[i][j] *= corr;
        }

        #pragma unroll
        for (int i = 0; i < 8; i++) {
            float* pp = &Ps[(ty * 8 + i) * PS_PITCH + tx * 8];
            *(float4*)&pp[0] = make_float4(s[i][0], s[i][1], s[i][2], s[i][3]);
            *(float4*)&pp[4] = make_float4(s[i][4], s[i][5], s[i][6], s[i][7]);
        }
        __syncthreads();

        #pragma unroll 4
        for (int kk = 0; kk < 128; kk++) {
            float bb[4];
            *(float4*)&bb[0] = *(const float4*)&Vs[kk * 64 + tx * 4];
            #pragma unroll
            for (int i = 0; i < 8; i++) {
                const float a = Ps[(ty * 8 + i) * PS_PITCH + kk];
                #pragma unroll
                for (int j = 0; j < 4; j++)
                    o[i][j] += a * bb[j];
            }
        }
    }

    #pragma unroll
    for (int i = 0; i < 8; i++) {
        const float inv = 1.0f / l[i];
        const int row = qrow0 + ty * 8 + i;
        float* cp = ctx + (size_t)row * D_MODEL + h * HD + tx * 4;
        #pragma unroll
        for (int j = 0; j < 4; j++)
            cp[j] = tf32r(o[i][j] * inv);   // pre-round for the Wo tf32 GEMM
    }
}

// =================================================================
extern "C" void kernel_launch(void* const* d_in, const int* in_sizes, int n_in,
                              void* d_out, int out_size)
{
    const float* x  = (const float*)d_in[0];
    const float* Wq = (const float*)d_in[1];
    const float* bq = (const float*)d_in[2];
    const float* Wk = (const float*)d_in[3];
    const float* bk = (const float*)d_in[4];
    const float* Wv = (const float*)d_in[5];
    const float* bv = (const float*)d_in[6];
    const float* Wo = (const float*)d_in[7];
    const float* bo = (const float*)d_in[8];
    float* out = (float*)d_out;

    float *qp, *kp, *vp, *cp, *xr, *wt;
    cudaGetSymbolAddress((void**)&qp, g_q);
    cudaGetSymbolAddress((void**)&kp, g_k);
    cudaGetSymbolAddress((void**)&vp, g_v);
    cudaGetSymbolAddress((void**)&cp, g_ctx);
    cudaGetSymbolAddress((void**)&xr, g_xr);
    cudaGetSymbolAddress((void**)&wt, g_wt);

    cudaFuncSetAttribute(attn_kernel,
                         cudaFuncAttributeMaxDynamicSharedMemorySize, ATTN_SMEM_BYTES);
    cudaFuncSetAttribute(gemm_mma_kernel,
                         cudaFuncAttributeMaxDynamicSharedMemorySize, GEMM_SMEM);

    // round x once
    {
        int n4 = MTOT * D_MODEL / 4;
        round_copy_kernel<<<(n4 + 255) / 256, 256>>>((const float4*)x, (float4*)xr, n4);
    }

    dim3 tb(32, 8);

    // Q projection
    transpose_round_kernel<<<dim3(D_MODEL / 32, D_MODEL / 32), tb>>>(Wq, wt, D_MODEL, D_MODEL);
    gemm_mma_kernel<<<dim3(D_MODEL / 128, MTOT / 128), 256, GEMM_SMEM>>>(
        xr, wt, bq, qp, MTOT, D_MODEL, D_MODEL);
    // K projection
    transpose_round_kernel<<<dim3(KV_DIM / 32, D_MODEL / 32), tb>>>(Wk, wt, D_MODEL, KV_DIM);
    gemm_mma_kernel<<<dim3(KV_DIM / 128, MTOT / 128), 256, GEMM_SMEM>>>(
        xr, wt, bk, kp, MTOT, KV_DIM, D_MODEL);
    // V projection
    transpose_round_kernel<<<dim3(KV_DIM / 32, D_MODEL / 32), tb>>>(Wv, wt, D_MODEL, KV_DIM);
    gemm_mma_kernel<<<dim3(KV_DIM / 128, MTOT / 128), 256, GEMM_SMEM>>>(
        xr, wt, bv, vp, MTOT, KV_DIM, D_MODEL);

    // attention (fp32, writes tf32-rounded ctx)
    attn_kernel<<<dim3(SEQ / 128, NHEADS, BATCH), 256, ATTN_SMEM_BYTES>>>(qp, kp, vp, cp);

    // output projection
    transpose_round_kernel<<<dim3(D_MODEL / 32, D_MODEL / 32), tb>>>(Wo, wt, D_MODEL, D_MODEL);
    gemm_mma_kernel<<<dim3(D_MODEL / 128, MTOT / 128), 256, GEMM_SMEM>>>(
        cp, wt, bo, out, MTOT, D_MODEL, D_MODEL);
}

// round 4
// speedup vs baseline: 2.0537x; 1.3698x over previous
#include <cuda_runtime.h>
#include <cstdint>

#define D_MODEL 2048
#define KV_DIM  512
#define NHEADS  32
#define NKVH    8
#define HD      64
#define SEQ     1024
#define BATCH   4
#define MTOT    (BATCH * SEQ)   // 4096

// ---------------- scratch (no cudaMalloc allowed) ----------------
__device__ __align__(256) float g_q[MTOT * D_MODEL];
__device__ __align__(256) float g_k[MTOT * KV_DIM];
__device__ __align__(256) float g_v[MTOT * KV_DIM];
__device__ __align__(256) float g_ctx[MTOT * D_MODEL];
__device__ __align__(256) float g_xr[MTOT * D_MODEL];     // tf32-rounded x
__device__ __align__(256) float g_wt[D_MODEL * D_MODEL];  // transposed+rounded weight (reused)

// ================= helpers =================
__device__ __forceinline__ uint32_t smem_u32(const void* p) {
    uint32_t a;
    asm("{ .reg .u64 t; cvta.to.shared.u64 t, %1; cvt.u32.u64 %0, t; }" : "=r"(a) : "l"(p));
    return a;
}
__device__ __forceinline__ float tf32r(float x) {
    float y;
    asm("cvt.rna.tf32.f32 %0, %1;" : "=f"(y) : "f"(x));
    return y;
}
__device__ __forceinline__ void mma_tf32(float c[4], uint32_t a0, uint32_t a1,
                                         uint32_t a2, uint32_t a3,
                                         uint32_t b0, uint32_t b1) {
    asm volatile(
        "mma.sync.aligned.m16n8k8.row.col.f32.tf32.tf32.f32 "
        "{%0,%1,%2,%3}, {%4,%5,%6,%7}, {%8,%9}, {%0,%1,%2,%3};"
        : "+f"(c[0]), "+f"(c[1]), "+f"(c[2]), "+f"(c[3])
        : "r"(a0), "r"(a1), "r"(a2), "r"(a3), "r"(b0), "r"(b1));
}

// ================= prep kernels =================
__global__ void round_copy_kernel(const float4* __restrict__ in, float4* __restrict__ out, int n4) {
    int i = blockIdx.x * blockDim.x + threadIdx.x;
    if (i < n4) {
        float4 v = in[i];
        v.x = tf32r(v.x); v.y = tf32r(v.y); v.z = tf32r(v.z); v.w = tf32r(v.w);
        out[i] = v;
    }
}

// W [K, N] row-major -> Wt [N, K] row-major, tf32-rounded
__global__ void transpose_round_kernel(const float* __restrict__ W, float* __restrict__ Wt,
                                       int K, int N) {
    __shared__ float t[32][33];
    const int n0 = blockIdx.x * 32, k0 = blockIdx.y * 32;
    const int tx = threadIdx.x, ty = threadIdx.y;  // 32 x 8
    #pragma unroll
    for (int i = 0; i < 32; i += 8)
        t[ty + i][tx] = W[(size_t)(k0 + ty + i) * N + n0 + tx];
    __syncthreads();
    #pragma unroll
    for (int i = 0; i < 32; i += 8)
        Wt[(size_t)(n0 + ty + i) * K + k0 + tx] = tf32r(t[tx][ty + i]);
}

// ================= warp-MMA tf32 GEMM =================
// C[M,N] = A[M,K] @ Bt[N,K]^T + bias.  A, Bt pre-rounded to tf32.
// 128x128 tile, BK=32, 8 warps (2 x 4 -> 64x32 each), 3-stage cp.async.
#define GS   3
#define GP   36
#define GA_STAGE      (128 * GP)
#define GSTAGE_FLOATS (2 * 128 * GP)
#define GEMM_SMEM     (GS * GSTAGE_FLOATS * 4)  // 110592 B

__global__ __launch_bounds__(256, 1) void gemm_mma_kernel(
    const float* __restrict__ A, const float* __restrict__ Bt,
    const float* __restrict__ bias, float* __restrict__ C,
    int M, int N, int K, int round_out)
{
    extern __shared__ __align__(16) float gsm[];

    const int tid  = threadIdx.x;
    const int wid  = tid >> 5;
    const int lane = tid & 31;
    const int m0 = blockIdx.y * 128;
    const int n0 = blockIdx.x * 128;
    const int wm = wid & 1;
    const int wn = wid >> 1;

    const bool isA = tid < 128;
    const int  row = isA ? tid : tid - 128;
    const float* gsrc = isA ? (A + (size_t)(m0 + row) * K)
                            : (Bt + (size_t)(n0 + row) * K);
    const uint32_t sdst_row = smem_u32(gsm) +
        ((isA ? 0 : GA_STAGE) + row * GP) * 4;

    const int nChunks = K / 32;

    #define GISSUE(ch, st) do {                                                \
        uint32_t _d = sdst_row + (st) * (GSTAGE_FLOATS * 4);                   \
        const float* _g = gsrc + (ch) * 32;                                    \
        _Pragma("unroll")                                                      \
        for (int _c = 0; _c < 8; _c++)                                         \
            asm volatile("cp.async.cg.shared.global [%0], [%1], 16;"           \
                         :: "r"(_d + _c * 16), "l"(_g + _c * 4) : "memory");   \
    } while (0)

    GISSUE(0, 0);
    asm volatile("cp.async.commit_group;" ::: "memory");
    GISSUE(1, 1);
    asm volatile("cp.async.commit_group;" ::: "memory");

    float acc[4][4][4];
    #pragma unroll
    for (int mi = 0; mi < 4; mi++)
        #pragma unroll
        for (int ni = 0; ni < 4; ni++)
            #pragma unroll
            for (int r = 0; r < 4; r++) acc[mi][ni][r] = 0.f;

    const int frow = lane >> 2;
    const int fcol = lane & 3;

    for (int ch = 0; ch < nChunks; ch++) {
        asm volatile("cp.async.wait_group 1;" ::: "memory");
        __syncthreads();
        if (ch + 2 < nChunks) GISSUE(ch + 2, (ch + 2) % GS);
        asm volatile("cp.async.commit_group;" ::: "memory");

        const float* As = gsm + (ch % GS) * GSTAGE_FLOATS;
        const float* Bs = As + GA_STAGE;

        #pragma unroll
        for (int ks = 0; ks < 4; ks++) {
            const int kb = ks * 8 + fcol;
            uint32_t a[4][4], b[4][2];
            #pragma unroll
            for (int mi = 0; mi < 4; mi++) {
                const float* p = As + (wm * 64 + mi * 16 + frow) * GP + kb;
                a[mi][0] = __float_as_uint(p[0]);
                a[mi][1] = __float_as_uint(p[8 * GP]);
                a[mi][2] = __float_as_uint(p[4]);
                a[mi][3] = __float_as_uint(p[8 * GP + 4]);
            }
            #pragma unroll
            for (int ni = 0; ni < 4; ni++) {
                const float* p = Bs + (wn * 32 + ni * 8 + frow) * GP + kb;
                b[ni][0] = __float_as_uint(p[0]);
                b[ni][1] = __float_as_uint(p[4]);
            }
            #pragma unroll
            for (int mi = 0; mi < 4; mi++)
                #pragma unroll
                for (int ni = 0; ni < 4; ni++)
                    mma_tf32(acc[mi][ni], a[mi][0], a[mi][1], a[mi][2], a[mi][3],
                             b[ni][0], b[ni][1]);
        }
    }
    #undef GISSUE

    #pragma unroll
    for (int mi = 0; mi < 4; mi++) {
        const int r0 = m0 + wm * 64 + mi * 16 + frow;
        #pragma unroll
        for (int ni = 0; ni < 4; ni++) {
            const int col = n0 + wn * 32 + ni * 8 + 2 * fcol;
            const float b0 = bias[col], b1 = bias[col + 1];
            float2 v0, v1;
            if (round_out) {
                v0 = make_float2(tf32r(acc[mi][ni][0] + b0), tf32r(acc[mi][ni][1] + b1));
                v1 = make_float2(tf32r(acc[mi][ni][2] + b0), tf32r(acc[mi][ni][3] + b1));
            } else {
                v0 = make_float2(acc[mi][ni][0] + b0, acc[mi][ni][1] + b1);
                v1 = make_float2(acc[mi][ni][2] + b0, acc[mi][ni][3] + b1);
            }
            *(float2*)(C + (size_t)r0 * N + col) = v0;
            *(float2*)(C + (size_t)(r0 + 8) * N + col) = v1;
        }
    }
}

// =================================================================
// Tensor-core flash attention (tf32 mma + fp32 softmax)
// Block = (b, h, 128 q-rows), 8 warps x 16 q-rows, full 128-key width.
// =================================================================
#define AP_Q 68     // 68 % 32 == 4 -> frag LDS bank == lane
#define AP_K 68
#define AP_V 72     // 72 % 32 == 8 -> banks 8*fcol+frow, all distinct
#define AP_P 132    // 132 % 32 == 4
#define SM_Q 0
#define SM_K (SM_Q + 128 * AP_Q)
#define SM_V (SM_K + 128 * AP_K)
#define SM_P (SM_V + 128 * AP_V)
#define ATTN_SMEM_FLOATS (SM_P + 128 * AP_P)
#define ATTN_SMEM_BYTES  (ATTN_SMEM_FLOATS * 4)   // 174080 B

__global__ __launch_bounds__(256, 1) void attn_mma_kernel(
    const float* __restrict__ q, const float* __restrict__ k,
    const float* __restrict__ v, float* __restrict__ ctx)
{
    extern __shared__ __align__(16) float sm[];

    const int tid  = threadIdx.x;
    const int wid  = tid >> 5;
    const int lane = tid & 31;
    const int frow = lane >> 2;
    const int fcol = lane & 3;
    const int qt = blockIdx.x;
    const int h  = blockIdx.y;
    const int b  = blockIdx.z;
    const int kvh = h >> 2;

    const int qrow0 = b * SEQ + qt * 128;
    const float* qbase = q + (size_t)qrow0 * D_MODEL + h * HD;
    const float* kbase = k + (size_t)b * SEQ * KV_DIM + kvh * HD;
    const float* vbase = v + (size_t)b * SEQ * KV_DIM + kvh * HD;

    const uint32_t smb = smem_u32(sm);
    const int srow = tid >> 1;          // 0..127
    const int sc0  = (tid & 1) * 8;     // chunk offset (8 x 16B = 32 floats)

    // ---- stage Q once ----
    {
        const float* g = qbase + (size_t)srow * D_MODEL + sc0 * 4;
        uint32_t d = smb + (SM_Q + srow * AP_Q) * 4 + sc0 * 16;
        #pragma unroll
        for (int c = 0; c < 8; c++)
            asm volatile("cp.async.cg.shared.global [%0], [%1], 16;"
                         :: "r"(d + c * 16), "l"(g + c * 4) : "memory");
        asm volatile("cp.async.commit_group;" ::: "memory");
    }

    float mrow[2] = {-1e30f, -1e30f};
    float lrow[2] = {0.f, 0.f};
    float accO[8][4];
    #pragma unroll
    for (int ni = 0; ni < 8; ni++)
        #pragma unroll
        for (int r = 0; r < 4; r++) accO[ni][r] = 0.f;

    for (int kt = 0; kt < SEQ / 128; kt++) {
        if (kt) __syncthreads();   // all warps done reading prev K/V
        // ---- stage K and V tiles ----
        {
            const float* gk = kbase + (size_t)(kt * 128 + srow) * KV_DIM + sc0 * 4;
            const float* gv = vbase + (size_t)(kt * 128 + srow) * KV_DIM + sc0 * 4;
            uint32_t dk = smb + (SM_K + srow * AP_K) * 4 + sc0 * 16;
            uint32_t dv = smb + (SM_V + srow * AP_V) * 4 + sc0 * 16;
            #pragma unroll
            for (int c = 0; c < 8; c++) {
                asm volatile("cp.async.cg.shared.global [%0], [%1], 16;"
                             :: "r"(dk + c * 16), "l"(gk + c * 4) : "memory");
                asm volatile("cp.async.cg.shared.global [%0], [%1], 16;"
                             :: "r"(dv + c * 16), "l"(gv + c * 4) : "memory");
            }
            asm volatile("cp.async.commit_group;" ::: "memory");
        }
        asm volatile("cp.async.wait_group 0;" ::: "memory");
        __syncthreads();

        // ---- S = Q @ K^T (warp: 16 q-rows x 128 keys, K=64) ----
        float accS[16][4];
        #pragma unroll
        for (int ni = 0; ni < 16; ni++)
            #pragma unroll
            for (int r = 0; r < 4; r++) accS[ni][r] = 0.f;

        const float* Qs = sm + SM_Q + (wid * 16) * AP_Q;
        const float* Ks = sm + SM_K;
        #pragma unroll
        for (int ks = 0; ks < 8; ks++) {
            const int kb = ks * 8 + fcol;
            uint32_t a0 = __float_as_uint(Qs[frow * AP_Q + kb]);
            uint32_t a1 = __float_as_uint(Qs[(frow + 8) * AP_Q + kb]);
            uint32_t a2 = __float_as_uint(Qs[frow * AP_Q + kb + 4]);
            uint32_t a3 = __float_as_uint(Qs[(frow + 8) * AP_Q + kb + 4]);
            #pragma unroll
            for (int ni = 0; ni < 16; ni++) {
                const float* p = Ks + (ni * 8 + frow) * AP_K + kb;
                mma_tf32(accS[ni], a0, a1, a2, a3,
                         __float_as_uint(p[0]), __float_as_uint(p[4]));
            }
        }

        // ---- streaming softmax (rows frow, frow+8 of this warp) ----
        float mx0 = -1e30f, mx1 = -1e30f;
        #pragma unroll
        for (int ni = 0; ni < 16; ni++) {
            #pragma unroll
            for (int r = 0; r < 4; r++) accS[ni][r] *= 0.125f;
            mx0 = fmaxf(mx0, fmaxf(accS[ni][0], accS[ni][1]));
            mx1 = fmaxf(mx1, fmaxf(accS[ni][2], accS[ni][3]));
        }
        mx0 = fmaxf(mx0, __shfl_xor_sync(0xffffffffu, mx0, 1));
        mx0 = fmaxf(mx0, __shfl_xor_sync(0xffffffffu, mx0, 2));
        mx1 = fmaxf(mx1, __shfl_xor_sync(0xffffffffu, mx1, 1));
        mx1 = fmaxf(mx1, __shfl_xor_sync(0xffffffffu, mx1, 2));

        const float mn0 = fmaxf(mrow[0], mx0);
        const float mn1 = fmaxf(mrow[1], mx1);
        const float corr0 = __expf(mrow[0] - mn0);
        const float corr1 = __expf(mrow[1] - mn1);
        mrow[0] = mn0; mrow[1] = mn1;

        float* Pw = sm + SM_P + (wid * 16) * AP_P;
        float sum0 = 0.f, sum1 = 0.f;
        #pragma unroll
        for (int ni = 0; ni < 16; ni++) {
            float p0 = __expf(accS[ni][0] - mn0);
            float p1 = __expf(accS[ni][1] - mn0);
            float p2 = __expf(accS[ni][2] - mn1);
            float p3 = __expf(accS[ni][3] - mn1);
            sum0 += p0 + p1;
            sum1 += p2 + p3;
            const int col = ni * 8 + 2 * fcol;
            Pw[frow * AP_P + col]       = tf32r(p0);
            Pw[frow * AP_P + col + 1]   = tf32r(p1);
            Pw[(frow + 8) * AP_P + col]     = tf32r(p2);
            Pw[(frow + 8) * AP_P + col + 1] = tf32r(p3);
        }
        sum0 += __shfl_xor_sync(0xffffffffu, sum0, 1);
        sum0 += __shfl_xor_sync(0xffffffffu, sum0, 2);
        sum1 += __shfl_xor_sync(0xffffffffu, sum1, 1);
        sum1 += __shfl_xor_sync(0xffffffffu, sum1, 2);
        lrow[0] = lrow[0] * corr0 + sum0;
        lrow[1] = lrow[1] * corr1 + sum1;

        #pragma unroll
        for (int ni = 0; ni < 8; ni++) {
            accO[ni][0] *= corr0; accO[ni][1] *= corr0;
            accO[ni][2] *= corr1; accO[ni][3] *= corr1;
        }
        __syncwarp();

        // ---- O += P @ V (warp: 16 rows x 64 d, K=128 keys) ----
        const float* Pr = sm + SM_P + (wid * 16) * AP_P;
        const float* Vs = sm + SM_V;
        #pragma unroll
        for (int ks = 0; ks < 16; ks++) {
            const int kb = ks * 8 + fcol;
            uint32_t a0 = __float_as_uint(Pr[frow * AP_P + kb]);
            uint32_t a1 = __float_as_uint(Pr[(frow + 8) * AP_P + kb]);
            uint32_t a2 = __float_as_uint(Pr[frow * AP_P + kb + 4]);
            uint32_t a3 = __float_as_uint(Pr[(frow + 8) * AP_P + kb + 4]);
            #pragma unroll
            for (int ni = 0; ni < 8; ni++) {
                // B[n][k] = V[k][n]; b0 at key kb, b1 at key kb+4
                uint32_t b0 = __float_as_uint(Vs[kb * AP_V + ni * 8 + frow]);
                uint32_t b1 = __float_as_uint(Vs[(kb + 4) * AP_V + ni * 8 + frow]);
                mma_tf32(accO[ni], a0, a1, a2, a3, b0, b1);
            }
        }
    }

    // ---- epilogue ----
    const float inv0 = 1.0f / lrow[0];
    const float inv1 = 1.0f / lrow[1];
    const int r0 = qrow0 + wid * 16 + frow;
    #pragma unroll
    for (int ni = 0; ni < 8; ni++) {
        const int col = h * HD + ni * 8 + 2 * fcol;
        float* c0p = ctx + (size_t)r0 * D_MODEL + col;
        float* c1p = ctx + (size_t)(r0 + 8) * D_MODEL + col;
        c0p[0] = tf32r(accO[ni][0] * inv0);
        c0p[1] = tf32r(accO[ni][1] * inv0);
        c1p[0] = tf32r(accO[ni][2] * inv1);
        c1p[1] = tf32r(accO[ni][3] * inv1);
    }
}

// =================================================================
extern "C" void kernel_launch(void* const* d_in, const int* in_sizes, int n_in,
                              void* d_out, int out_size)
{
    const float* x  = (const float*)d_in[0];
    const float* Wq = (const float*)d_in[1];
    const float* bq = (const float*)d_in[2];
    const float* Wk = (const float*)d_in[3];
    const float* bk = (const float*)d_in[4];
    const float* Wv = (const float*)d_in[5];
    const float* bv = (const float*)d_in[6];
    const float* Wo = (const float*)d_in[7];
    const float* bo = (const float*)d_in[8];
    float* out = (float*)d_out;

    float *qp, *kp, *vp, *cp, *xr, *wt;
    cudaGetSymbolAddress((void**)&qp, g_q);
    cudaGetSymbolAddress((void**)&kp, g_k);
    cudaGetSymbolAddress((void**)&vp, g_v);
    cudaGetSymbolAddress((void**)&cp, g_ctx);
    cudaGetSymbolAddress((void**)&xr, g_xr);
    cudaGetSymbolAddress((void**)&wt, g_wt);

    cudaFuncSetAttribute(attn_mma_kernel,
                         cudaFuncAttributeMaxDynamicSharedMemorySize, ATTN_SMEM_BYTES);
    cudaFuncSetAttribute(gemm_mma_kernel,
                         cudaFuncAttributeMaxDynamicSharedMemorySize, GEMM_SMEM);

    {
        int n4 = MTOT * D_MODEL / 4;
        round_copy_kernel<<<(n4 + 255) / 256, 256>>>((const float4*)x, (float4*)xr, n4);
    }

    dim3 tb(32, 8);

    // Q projection (round output -> attention consumes tf32-clean values)
    transpose_round_kernel<<<dim3(D_MODEL / 32, D_MODEL / 32), tb>>>(Wq, wt, D_MODEL, D_MODEL);
    gemm_mma_kernel<<<dim3(D_MODEL / 128, MTOT / 128), 256, GEMM_SMEM>>>(
        xr, wt, bq, qp, MTOT, D_MODEL, D_MODEL, 1);
    // K projection
    transpose_round_kernel<<<dim3(KV_DIM / 32, D_MODEL / 32), tb>>>(Wk, wt, D_MODEL, KV_DIM);
    gemm_mma_kernel<<<dim3(KV_DIM / 128, MTOT / 128), 256, GEMM_SMEM>>>(
        xr, wt, bk, kp, MTOT, KV_DIM, D_MODEL, 1);
    // V projection
    transpose_round_kernel<<<dim3(KV_DIM / 32, D_MODEL / 32), tb>>>(Wv, wt, D_MODEL, KV_DIM);
    gemm_mma_kernel<<<dim3(KV_DIM / 128, MTOT / 128), 256, GEMM_SMEM>>>(
        xr, wt, bv, vp, MTOT, KV_DIM, D_MODEL, 1);

    // attention (tensor-core, writes tf32-rounded ctx)
    attn_mma_kernel<<<dim3(SEQ / 128, NHEADS, BATCH), 256, ATTN_SMEM_BYTES>>>(qp, kp, vp, cp);

    // output projection (fp32 output)
    transpose_round_kernel<<<dim3(D_MODEL / 32, D_MODEL / 32), tb>>>(Wo, wt, D_MODEL, D_MODEL);
    gemm_mma_kernel<<<dim3(D_MODEL / 128, MTOT / 128), 256, GEMM_SMEM>>>(
        cp, wt, bo, out, MTOT, D_MODEL, D_MODEL, 0);
}

// round 6
// speedup vs baseline: 3.9199x; 1.9088x over previous
#include <cuda_runtime.h>
#include <cuda_fp16.h>
#include <cstdint>

#define D_MODEL 2048
#define KV_DIM  512
#define NHEADS  32
#define NKVH    8
#define HD      64
#define SEQ     1024
#define BATCH   4
#define MTOT    (BATCH * SEQ)   // 4096

// ---------------- scratch (no cudaMalloc allowed) ----------------
__device__ __align__(256) __half g_qh[MTOT * D_MODEL];
__device__ __align__(256) __half g_kh[MTOT * KV_DIM];
__device__ __align__(256) __half g_vh[MTOT * KV_DIM];
__device__ __align__(256) __half g_vt[MTOT * KV_DIM];     // V transposed [b][kvh][d][seq]
__device__ __align__(256) __half g_ch[MTOT * D_MODEL];    // attention ctx (fp16)
__device__ __align__(256) __half g_xh[MTOT * D_MODEL];    // x in fp16
__device__ __align__(256) __half g_wth[D_MODEL * D_MODEL];// transposed fp16 weight (reused)

// ================= helpers =================
__device__ __forceinline__ uint32_t smem_u32(const void* p) {
    uint32_t a;
    asm("{ .reg .u64 t; cvta.to.shared.u64 t, %1; cvt.u32.u64 %0, t; }" : "=r"(a) : "l"(p));
    return a;
}
__device__ __forceinline__ void mma_f16(float c[4], uint32_t a0, uint32_t a1,
                                        uint32_t a2, uint32_t a3,
                                        uint32_t b0, uint32_t b1) {
    asm volatile(
        "mma.sync.aligned.m16n8k16.row.col.f32.f16.f16.f32 "
        "{%0,%1,%2,%3}, {%4,%5,%6,%7}, {%8,%9}, {%0,%1,%2,%3};"
        : "+f"(c[0]), "+f"(c[1]), "+f"(c[2]), "+f"(c[3])
        : "r"(a0), "r"(a1), "r"(a2), "r"(a3), "r"(b0), "r"(b1));
}
__device__ __forceinline__ uint32_t ldu32(const __half* p) {
    return *(const uint32_t*)p;
}

// ================= prep kernels =================
__global__ void to_half_kernel(const float4* __restrict__ in, uint2* __restrict__ out, int n4) {
    int i = blockIdx.x * blockDim.x + threadIdx.x;
    if (i < n4) {
        float4 v = in[i];
        __half2 h0 = __floats2half2_rn(v.x, v.y);
        __half2 h1 = __floats2half2_rn(v.z, v.w);
        out[i] = make_uint2(*(uint32_t*)&h0, *(uint32_t*)&h1);
    }
}

// W [K, N] fp32 row-major -> Wt [N, K] fp16 row-major
__global__ void transpose_half_kernel(const float* __restrict__ W, __half* __restrict__ Wt,
                                      int K, int N) {
    __shared__ float t[32][33];
    const int n0 = blockIdx.x * 32, k0 = blockIdx.y * 32;
    const int tx = threadIdx.x, ty = threadIdx.y;  // 32 x 8
    #pragma unroll
    for (int i = 0; i < 32; i += 8)
        t[ty + i][tx] = W[(size_t)(k0 + ty + i) * N + n0 + tx];
    __syncthreads();
    #pragma unroll
    for (int i = 0; i < 32; i += 8)
        Wt[(size_t)(n0 + ty + i) * K + k0 + tx] = __float2half_rn(t[tx][ty + i]);
}

// v [MTOT][KV_DIM] fp16 -> vt [(b*KV_DIM + c)][SEQ] fp16   (c = kvh*64 + d)
__global__ void vtrans_kernel(const __half* __restrict__ v, __half* __restrict__ vt) {
    __shared__ __half t[32][34];
    const int s0 = blockIdx.x * 32, c0 = blockIdx.y * 32, b = blockIdx.z;
    const int tx = threadIdx.x, ty = threadIdx.y;  // 32 x 8
    #pragma unroll
    for (int i = 0; i < 32; i += 8)
        t[ty + i][tx] = v[(size_t)(b * SEQ + s0 + ty + i) * KV_DIM + c0 + tx];
    __syncthreads();
    #pragma unroll
    for (int i = 0; i < 32; i += 8)
        vt[(size_t)(b * KV_DIM + c0 + ty + i) * SEQ + s0 + tx] = t[tx][ty + i];
}

// ================= fp16 warp-MMA GEMM =================
// C = A_h[M,K] @ Bt_h[N,K]^T + bias.  128x128 tile, BK=64 halfs,
// 8 warps (2x4 -> 64x32 each), 3-stage cp.async. Pitch 72 halfs (144 B).
#define GS   3
#define GPH  72
#define GA_STAGE (128 * GPH)            // halfs
#define GSTAGE_H (2 * 128 * GPH)
#define GEMM_SMEM (GS * GSTAGE_H * 2)   // 110592 B

__global__ __launch_bounds__(256, 1) void gemm_h_kernel(
    const __half* __restrict__ A, const __half* __restrict__ Bt,
    const float* __restrict__ bias, float* __restrict__ Cf, __half* __restrict__ Ch,
    int M, int N, int K, int outHalf)
{
    extern __shared__ __align__(16) __half hsm[];

    const int tid  = threadIdx.x;
    const int wid  = tid >> 5;
    const int lane = tid & 31;
    const int m0 = blockIdx.y * 128;
    const int n0 = blockIdx.x * 128;
    const int wm = wid & 1;
    const int wn = wid >> 1;
    const int frow = lane >> 2;
    const int t4   = lane & 3;

    const bool isA = tid < 128;
    const int  row = isA ? tid : tid - 128;
    const __half* gsrc = isA ? (A + (size_t)(m0 + row) * K)
                             : (Bt + (size_t)(n0 + row) * K);
    const uint32_t sdst_row = smem_u32(hsm) + ((isA ? 0 : GA_STAGE) + row * GPH) * 2;

    const int nChunks = K / 64;

    #define GISSUE(ch, st) do {                                                \
        uint32_t _d = sdst_row + (st) * (GSTAGE_H * 2);                        \
        const __half* _g = gsrc + (ch) * 64;                                   \
        _Pragma("unroll")                                                      \
        for (int _c = 0; _c < 8; _c++)                                         \
            asm volatile("cp.async.cg.shared.global [%0], [%1], 16;"           \
                         :: "r"(_d + _c * 16), "l"(_g + _c * 8) : "memory");   \
    } while (0)

    GISSUE(0, 0);
    asm volatile("cp.async.commit_group;" ::: "memory");
    GISSUE(1, 1);
    asm volatile("cp.async.commit_group;" ::: "memory");

    float acc[4][4][4];
    #pragma unroll
    for (int mi = 0; mi < 4; mi++)
        #pragma unroll
        for (int ni = 0; ni < 4; ni++)
            #pragma unroll
            for (int r = 0; r < 4; r++) acc[mi][ni][r] = 0.f;

    for (int ch = 0; ch < nChunks; ch++) {
        asm volatile("cp.async.wait_group 1;" ::: "memory");
        __syncthreads();
        if (ch + 2 < nChunks) GISSUE(ch + 2, (ch + 2) % GS);
        asm volatile("cp.async.commit_group;" ::: "memory");

        const __half* As = hsm + (ch % GS) * GSTAGE_H;
        const __half* Bs = As + GA_STAGE;

        #pragma unroll
        for (int ks = 0; ks < 4; ks++) {
            const int kb = ks * 16 + 2 * t4;
            uint32_t a[4][4], b[4][2];
            #pragma unroll
            for (int mi = 0; mi < 4; mi++) {
                const __half* p = As + (wm * 64 + mi * 16 + frow) * GPH + kb;
                a[mi][0] = ldu32(p);
                a[mi][1] = ldu32(p + 8 * GPH);
                a[mi][2] = ldu32(p + 8);
                a[mi][3] = ldu32(p + 8 * GPH + 8);
            }
            #pragma unroll
            for (int ni = 0; ni < 4; ni++) {
                const __half* p = Bs + (wn * 32 + ni * 8 + frow) * GPH + kb;
                b[ni][0] = ldu32(p);
                b[ni][1] = ldu32(p + 8);
            }
            #pragma unroll
            for (int mi = 0; mi < 4; mi++)
                #pragma unroll
                for (int ni = 0; ni < 4; ni++)
                    mma_f16(acc[mi][ni], a[mi][0], a[mi][1], a[mi][2], a[mi][3],
                            b[ni][0], b[ni][1]);
        }
    }
    #undef GISSUE

    #pragma unroll
    for (int mi = 0; mi < 4; mi++) {
        const int r0 = m0 + wm * 64 + mi * 16 + frow;
        #pragma unroll
        for (int ni = 0; ni < 4; ni++) {
            const int col = n0 + wn * 32 + ni * 8 + 2 * t4;
            const float b0 = bias[col], b1 = bias[col + 1];
            const float v00 = acc[mi][ni][0] + b0, v01 = acc[mi][ni][1] + b1;
            const float v10 = acc[mi][ni][2] + b0, v11 = acc[mi][ni][3] + b1;
            if (outHalf) {
                __half2 h0 = __floats2half2_rn(v00, v01);
                __half2 h1 = __floats2half2_rn(v10, v11);
                *(__half2*)(Ch + (size_t)r0 * N + col) = h0;
                *(__half2*)(Ch + (size_t)(r0 + 8) * N + col) = h1;
            } else {
                *(float2*)(Cf + (size_t)r0 * N + col) = make_float2(v00, v01);
                *(float2*)(Cf + (size_t)(r0 + 8) * N + col) = make_float2(v10, v11);
            }
        }
    }
}

// =================================================================
// fp16 tensor-core flash attention.
// Block = (b, h, 128 q-rows), 8 warps x 16 q-rows, full 128-key width.
// =================================================================
#define AQ 72      // Q/K pitch (halfs): 144 B
#define AV 136     // Vt/P pitch (halfs): 272 B
#define SQ 0
#define SK (SQ + 128 * AQ)
#define SV (SK + 128 * AQ)
#define SP (SV + 64 * AV)
#define ATTN_HALFS (SP + 128 * AV)
#define ATTN_SMEM_BYTES (ATTN_HALFS * 2)   // 89088 B

__global__ __launch_bounds__(256, 1) void attn_h_kernel(
    const __half* __restrict__ q, const __half* __restrict__ k,
    const __half* __restrict__ vt, __half* __restrict__ ctx)
{
    extern __shared__ __align__(16) __half hsm[];

    const int tid  = threadIdx.x;
    const int wid  = tid >> 5;
    const int lane = tid & 31;
    const int frow = lane >> 2;
    const int t4   = lane & 3;
    const int qt = blockIdx.x;
    const int h  = blockIdx.y;
    const int b  = blockIdx.z;
    const int kvh = h >> 2;

    const int qrow0 = b * SEQ + qt * 128;
    const __half* qbase = q + (size_t)qrow0 * D_MODEL + h * HD;
    const __half* kbase = k + (size_t)b * SEQ * KV_DIM + kvh * HD;
    const __half* vtbase = vt + (size_t)(b * KV_DIM + kvh * HD) * SEQ;

    const uint32_t smb = smem_u32(hsm);
    const int srow = tid >> 1;          // 0..127
    const int sc   = (tid & 1) * 32;    // halfs: each thread covers 32 halfs = 64 B

    // ---- stage Q once (128 rows x 128 B) ----
    {
        const __half* g = qbase + (size_t)srow * D_MODEL + sc;
        uint32_t d = smb + (SQ + srow * AQ + sc) * 2;
        #pragma unroll
        for (int c = 0; c < 4; c++)
            asm volatile("cp.async.cg.shared.global [%0], [%1], 16;"
                         :: "r"(d + c * 16), "l"(g + c * 8) : "memory");
        asm volatile("cp.async.commit_group;" ::: "memory");
    }

    float mrow[2] = {-1e30f, -1e30f};
    float lrow[2] = {0.f, 0.f};
    float accO[8][4];
    #pragma unroll
    for (int ni = 0; ni < 8; ni++)
        #pragma unroll
        for (int r = 0; r < 4; r++) accO[ni][r] = 0.f;

    const int vrow = tid >> 2;          // 0..63
    const int vc   = (tid & 3) * 32;    // halfs (quarter of a 256-B row)

    for (int kt = 0; kt < SEQ / 128; kt++) {
        if (kt) __syncthreads();
        // ---- stage K tile (128 x 128 B) and Vt tile (64 x 256 B) ----
        {
            const __half* gk = kbase + (size_t)(kt * 128 + srow) * KV_DIM + sc;
            uint32_t dk = smb + (SK + srow * AQ + sc) * 2;
            #pragma unroll
            for (int c = 0; c < 4; c++)
                asm volatile("cp.async.cg.shared.global [%0], [%1], 16;"
                             :: "r"(dk + c * 16), "l"(gk + c * 8) : "memory");
            const __half* gv = vtbase + (size_t)vrow * SEQ + kt * 128 + vc;
            uint32_t dv = smb + (SV + vrow * AV + vc) * 2;
            #pragma unroll
            for (int c = 0; c < 4; c++)
                asm volatile("cp.async.cg.shared.global [%0], [%1], 16;"
                             :: "r"(dv + c * 16), "l"(gv + c * 8) : "memory");
            asm volatile("cp.async.commit_group;" ::: "memory");
        }
        asm volatile("cp.async.wait_group 0;" ::: "memory");
        __syncthreads();

        // ---- S = Q @ K^T (warp: 16 q-rows x 128 keys, K = 64 = 4 k16 steps) ----
        float accS[16][4];
        #pragma unroll
        for (int ni = 0; ni < 16; ni++)
            #pragma unroll
            for (int r = 0; r < 4; r++) accS[ni][r] = 0.f;

        const __half* Qs = hsm + SQ + (wid * 16) * AQ;
        const __half* Ks = hsm + SK;
        #pragma unroll
        for (int ks = 0; ks < 4; ks++) {
            const int kb = ks * 16 + 2 * t4;
            const __half* pq = Qs + frow * AQ + kb;
            uint32_t a0 = ldu32(pq);
            uint32_t a1 = ldu32(pq + 8 * AQ);
            uint32_t a2 = ldu32(pq + 8);
            uint32_t a3 = ldu32(pq + 8 * AQ + 8);
            #pragma unroll
            for (int ni = 0; ni < 16; ni++) {
                const __half* pk = Ks + (ni * 8 + frow) * AQ + kb;
                mma_f16(accS[ni], a0, a1, a2, a3, ldu32(pk), ldu32(pk + 8));
            }
        }

        // ---- streaming softmax (rows frow, frow+8 of this warp) ----
        float mx0 = -1e30f, mx1 = -1e30f;
        #pragma unroll
        for (int ni = 0; ni < 16; ni++) {
            #pragma unroll
            for (int r = 0; r < 4; r++) accS[ni][r] *= 0.125f;
            mx0 = fmaxf(mx0, fmaxf(accS[ni][0], accS[ni][1]));
            mx1 = fmaxf(mx1, fmaxf(accS[ni][2], accS[ni][3]));
        }
        mx0 = fmaxf(mx0, __shfl_xor_sync(0xffffffffu, mx0, 1));
        mx0 = fmaxf(mx0, __shfl_xor_sync(0xffffffffu, mx0, 2));
        mx1 = fmaxf(mx1, __shfl_xor_sync(0xffffffffu, mx1, 1));
        mx1 = fmaxf(mx1, __shfl_xor_sync(0xffffffffu, mx1, 2));

        const float mn0 = fmaxf(mrow[0], mx0);
        const float mn1 = fmaxf(mrow[1], mx1);
        const float corr0 = __expf(mrow[0] - mn0);
        const float corr1 = __expf(mrow[1] - mn1);
        mrow[0] = mn0; mrow[1] = mn1;

        __half* Pw = hsm + SP + (wid * 16) * AV;
        float sum0 = 0.f, sum1 = 0.f;
        #pragma unroll
        for (int ni = 0; ni < 16; ni++) {
            float p0 = __expf(accS[ni][0] - mn0);
            float p1 = __expf(accS[ni][1] - mn0);
            float p2 = __expf(accS[ni][2] - mn1);
            float p3 = __expf(accS[ni][3] - mn1);
            sum0 += p0 + p1;
            sum1 += p2 + p3;
            const int col = ni * 8 + 2 * t4;
            *(__half2*)(Pw + frow * AV + col)       = __floats2half2_rn(p0, p1);
            *(__half2*)(Pw + (frow + 8) * AV + col) = __floats2half2_rn(p2, p3);
        }
        sum0 += __shfl_xor_sync(0xffffffffu, sum0, 1);
        sum0 += __shfl_xor_sync(0xffffffffu, sum0, 2);
        sum1 += __shfl_xor_sync(0xffffffffu, sum1, 1);
        sum1 += __shfl_xor_sync(0xffffffffu, sum1, 2);
        lrow[0] = lrow[0] * corr0 + sum0;
        lrow[1] = lrow[1] * corr1 + sum1;

        #pragma unroll
        for (int ni = 0; ni < 8; ni++) {
            accO[ni][0] *= corr0; accO[ni][1] *= corr0;
            accO[ni][2] *= corr1; accO[ni][3] *= corr1;
        }
        __syncwarp();

        // ---- O += P @ V (warp: 16 rows x 64 d, K = 128 keys = 8 k16 steps) ----
        const __half* Pr = hsm + SP + (wid * 16) * AV;
        const __half* Vs = hsm + SV;
        #pragma unroll
        for (int ks = 0; ks < 8; ks++) {
            const int kb = ks * 16 + 2 * t4;
            const __half* pp = Pr + frow * AV + kb;
            uint32_t a0 = ldu32(pp);
            uint32_t a1 = ldu32(pp + 8 * AV);
            uint32_t a2 = ldu32(pp + 8);
            uint32_t a3 = ldu32(pp + 8 * AV + 8);
            #pragma unroll
            for (int ni = 0; ni < 8; ni++) {
                const __half* pv = Vs + (ni * 8 + frow) * AV + kb;
                mma_f16(accO[ni], a0, a1, a2, a3, ldu32(pv), ldu32(pv + 8));
            }
        }
    }

    // ---- epilogue: ctx in fp16, [B*S][D_MODEL] ----
    const float inv0 = 1.0f / lrow[0];
    const float inv1 = 1.0f / lrow[1];
    const int r0 = qrow0 + wid * 16 + frow;
    #pragma unroll
    for (int ni = 0; ni < 8; ni++) {
        const int col = h * HD + ni * 8 + 2 * t4;
        *(__half2*)(ctx + (size_t)r0 * D_MODEL + col) =
            __floats2half2_rn(accO[ni][0] * inv0, accO[ni][1] * inv0);
        *(__half2*)(ctx + (size_t)(r0 + 8) * D_MODEL + col) =
            __floats2half2_rn(accO[ni][2] * inv1, accO[ni][3] * inv1);
    }
}

// =================================================================
extern "C" void kernel_launch(void* const* d_in, const int* in_sizes, int n_in,
                              void* d_out, int out_size)
{
    const float* x  = (const float*)d_in[0];
    const float* Wq = (const float*)d_in[1];
    const float* bq = (const float*)d_in[2];
    const float* Wk = (const float*)d_in[3];
    const float* bk = (const float*)d_in[4];
    const float* Wv = (const float*)d_in[5];
    const float* bv = (const float*)d_in[6];
    const float* Wo = (const float*)d_in[7];
    const float* bo = (const float*)d_in[8];
    float* out = (float*)d_out;

    __half *qh, *kh, *vh, *vtg, *ch, *xh, *wth;
    cudaGetSymbolAddress((void**)&qh,  g_qh);
    cudaGetSymbolAddress((void**)&kh,  g_kh);
    cudaGetSymbolAddress((void**)&vh,  g_vh);
    cudaGetSymbolAddress((void**)&vtg, g_vt);
    cudaGetSymbolAddress((void**)&ch,  g_ch);
    cudaGetSymbolAddress((void**)&xh,  g_xh);
    cudaGetSymbolAddress((void**)&wth, g_wth);

    cudaFuncSetAttribute(attn_h_kernel,
                         cudaFuncAttributeMaxDynamicSharedMemorySize, ATTN_SMEM_BYTES);
    cudaFuncSetAttribute(gemm_h_kernel,
                         cudaFuncAttributeMaxDynamicSharedMemorySize, GEMM_SMEM);

    {
        int n4 = MTOT * D_MODEL / 4;
        to_half_kernel<<<(n4 + 255) / 256, 256>>>((const float4*)x, (uint2*)xh, n4);
    }

    dim3 tb(32, 8);

    // Q projection
    transpose_half_kernel<<<dim3(D_MODEL / 32, D_MODEL / 32), tb>>>(Wq, wth, D_MODEL, D_MODEL);
    gemm_h_kernel<<<dim3(D_MODEL / 128, MTOT / 128), 256, GEMM_SMEM>>>(
        xh, wth, bq, nullptr, qh, MTOT, D_MODEL, D_MODEL, 1);
    // K projection
    transpose_half_kernel<<<dim3(KV_DIM / 32, D_MODEL / 32), tb>>>(Wk, wth, D_MODEL, KV_DIM);
    gemm_h_kernel<<<dim3(KV_DIM / 128, MTOT / 128), 256, GEMM_SMEM>>>(
        xh, wth, bk, nullptr, kh, MTOT, KV_DIM, D_MODEL, 1);
    // V projection
    transpose_half_kernel<<<dim3(KV_DIM / 32, D_MODEL / 32), tb>>>(Wv, wth, D_MODEL, KV_DIM);
    gemm_h_kernel<<<dim3(KV_DIM / 128, MTOT / 128), 256, GEMM_SMEM>>>(
        xh, wth, bv, nullptr, vh, MTOT, KV_DIM, D_MODEL, 1);

    // V transpose for fp16 B-fragments
    vtrans_kernel<<<dim3(SEQ / 32, KV_DIM / 32, BATCH), tb>>>(vh, vtg);

    // attention
    attn_h_kernel<<<dim3(SEQ / 128, NHEADS, BATCH), 256, ATTN_SMEM_BYTES>>>(qh, kh, vtg, ch);

    // output projection (fp32 out)
    transpose_half_kernel<<<dim3(D_MODEL / 32, D_MODEL / 32), tb>>>(Wo, wth, D_MODEL, D_MODEL);
    gemm_h_kernel<<<dim3(D_MODEL / 128, MTOT / 128), 256, GEMM_SMEM>>>(
        ch, wth, bo, out, nullptr, MTOT, D_MODEL, D_MODEL, 0);
}

// round 7
// speedup vs baseline: 4.1705x; 1.0639x over previous
#include <cuda_runtime.h>
#include <cuda_fp16.h>
#include <cstdint>

#define D_MODEL 2048
#define KV_DIM  512
#define NHEADS  32
#define NKVH    8
#define HD      64
#define SEQ     1024
#define BATCH   4
#define MTOT    (BATCH * SEQ)   // 4096

// ---------------- scratch (no cudaMalloc allowed) ----------------
__device__ __align__(256) __half g_qh[MTOT * D_MODEL];
__device__ __align__(256) __half g_kh[MTOT * KV_DIM];
__device__ __align__(256) __half g_vh[MTOT * KV_DIM];
__device__ __align__(256) __half g_vt[MTOT * KV_DIM];     // V transposed [b][kvh][d][seq]
__device__ __align__(256) __half g_ch[MTOT * D_MODEL];    // attention ctx (fp16)
__device__ __align__(256) __half g_xh[MTOT * D_MODEL];    // x in fp16
__device__ __align__(256) __half g_wth[D_MODEL * D_MODEL];// transposed fp16 weight (reused)

// ================= helpers =================
__device__ __forceinline__ uint32_t smem_u32(const void* p) {
    uint32_t a;
    asm("{ .reg .u64 t; cvta.to.shared.u64 t, %1; cvt.u32.u64 %0, t; }" : "=r"(a) : "l"(p));
    return a;
}
__device__ __forceinline__ void mma_f16(float c[4], uint32_t a0, uint32_t a1,
                                        uint32_t a2, uint32_t a3,
                                        uint32_t b0, uint32_t b1) {
    asm volatile(
        "mma.sync.aligned.m16n8k16.row.col.f32.f16.f16.f32 "
        "{%0,%1,%2,%3}, {%4,%5,%6,%7}, {%8,%9}, {%0,%1,%2,%3};"
        : "+f"(c[0]), "+f"(c[1]), "+f"(c[2]), "+f"(c[3])
        : "r"(a0), "r"(a1), "r"(a2), "r"(a3), "r"(b0), "r"(b1));
}
__device__ __forceinline__ void ldm_x4(uint32_t& r0, uint32_t& r1,
                                       uint32_t& r2, uint32_t& r3, uint32_t addr) {
    asm volatile("ldmatrix.sync.aligned.m8n8.x4.shared.b16 {%0,%1,%2,%3}, [%4];"
                 : "=r"(r0), "=r"(r1), "=r"(r2), "=r"(r3) : "r"(addr));
}

// ================= prep kernels =================
__global__ void to_half_kernel(const float4* __restrict__ in, uint2* __restrict__ out, int n4) {
    int i = blockIdx.x * blockDim.x + threadIdx.x;
    if (i < n4) {
        float4 v = in[i];
        __half2 h0 = __floats2half2_rn(v.x, v.y);
        __half2 h1 = __floats2half2_rn(v.z, v.w);
        out[i] = make_uint2(*(uint32_t*)&h0, *(uint32_t*)&h1);
    }
}

// W [K, N] fp32 row-major -> Wt [N, K] fp16 row-major
__global__ void transpose_half_kernel(const float* __restrict__ W, __half* __restrict__ Wt,
                                      int K, int N) {
    __shared__ float t[32][33];
    const int n0 = blockIdx.x * 32, k0 = blockIdx.y * 32;
    const int tx = threadIdx.x, ty = threadIdx.y;  // 32 x 8
    #pragma unroll
    for (int i = 0; i < 32; i += 8)
        t[ty + i][tx] = W[(size_t)(k0 + ty + i) * N + n0 + tx];
    __syncthreads();
    #pragma unroll
    for (int i = 0; i < 32; i += 8)
        Wt[(size_t)(n0 + ty + i) * K + k0 + tx] = __float2half_rn(t[tx][ty + i]);
}

// v [MTOT][KV_DIM] fp16 -> vt [(b*KV_DIM + c)][SEQ] fp16   (c = kvh*64 + d)
__global__ void vtrans_kernel(const __half* __restrict__ v, __half* __restrict__ vt) {
    __shared__ __half t[32][34];
    const int s0 = blockIdx.x * 32, c0 = blockIdx.y * 32, b = blockIdx.z;
    const int tx = threadIdx.x, ty = threadIdx.y;  // 32 x 8
    #pragma unroll
    for (int i = 0; i < 32; i += 8)
        t[ty + i][tx] = v[(size_t)(b * SEQ + s0 + ty + i) * KV_DIM + c0 + tx];
    __syncthreads();
    #pragma unroll
    for (int i = 0; i < 32; i += 8)
        vt[(size_t)(b * KV_DIM + c0 + ty + i) * SEQ + s0 + tx] = t[tx][ty + i];
}

// ================= fp16 warp-MMA GEMM (ldmatrix) =================
// C = A_h[M,K] @ Bt_h[N,K]^T + bias.  128x128 tile, BK=64 halfs,
// 8 warps (2x4 -> 64x32 each), 3-stage cp.async. Pitch 72 halfs (144 B).
#define GS   3
#define GPH  72
#define GA_STAGE (128 * GPH)            // halfs
#define GSTAGE_H (2 * 128 * GPH)
#define GEMM_SMEM (GS * GSTAGE_H * 2)   // 110592 B

__global__ __launch_bounds__(256, 1) void gemm_h_kernel(
    const __half* __restrict__ A, const __half* __restrict__ Bt,
    const float* __restrict__ bias, float* __restrict__ Cf, __half* __restrict__ Ch,
    int M, int N, int K, int outHalf)
{
    extern __shared__ __align__(16) __half hsm[];

    const int tid  = threadIdx.x;
    const int wid  = tid >> 5;
    const int lane = tid & 31;
    const int m0 = blockIdx.y * 128;
    const int n0 = blockIdx.x * 128;
    const int wm = wid & 1;
    const int wn = wid >> 1;
    const int frow = lane >> 2;
    const int t4   = lane & 3;

    const bool isA = tid < 128;
    const int  row = isA ? tid : tid - 128;
    const __half* gsrc = isA ? (A + (size_t)(m0 + row) * K)
                             : (Bt + (size_t)(n0 + row) * K);
    const uint32_t smem_base = smem_u32(hsm);
    const uint32_t sdst_row = smem_base + ((isA ? 0 : GA_STAGE) + row * GPH) * 2;

    // ldmatrix lane offsets (bytes, relative to stage A/B base)
    uint32_t aOff[4];
    #pragma unroll
    for (int mi = 0; mi < 4; mi++)
        aOff[mi] = ((wm * 64 + mi * 16 + (lane & 15)) * GPH + (lane >> 4) * 8) * 2;
    const uint32_t bOff = ((wn * 32 + (lane >> 3) * 8 + (lane & 7)) * GPH) * 2;

    const int nChunks = K / 64;

    #define GISSUE(ch, st) do {                                                \
        uint32_t _d = sdst_row + (st) * (GSTAGE_H * 2);                        \
        const __half* _g = gsrc + (ch) * 64;                                   \
        _Pragma("unroll")                                                      \
        for (int _c = 0; _c < 8; _c++)                                         \
            asm volatile("cp.async.cg.shared.global [%0], [%1], 16;"           \
                         :: "r"(_d + _c * 16), "l"(_g + _c * 8) : "memory");   \
    } while (0)

    GISSUE(0, 0);
    asm volatile("cp.async.commit_group;" ::: "memory");
    GISSUE(1, 1);
    asm volatile("cp.async.commit_group;" ::: "memory");

    float acc[4][4][4];
    #pragma unroll
    for (int mi = 0; mi < 4; mi++)
        #pragma unroll
        for (int ni = 0; ni < 4; ni++)
            #pragma unroll
            for (int r = 0; r < 4; r++) acc[mi][ni][r] = 0.f;

    for (int ch = 0; ch < nChunks; ch++) {
        asm volatile("cp.async.wait_group 1;" ::: "memory");
        __syncthreads();
        if (ch + 2 < nChunks) GISSUE(ch + 2, (ch + 2) % GS);
        asm volatile("cp.async.commit_group;" ::: "memory");

        const uint32_t stA = smem_base + (ch % GS) * (GSTAGE_H * 2);
        const uint32_t stB = stA + GA_STAGE * 2;

        #pragma unroll
        for (int ks = 0; ks < 4; ks++) {
            const uint32_t kb = ks * 32;   // bytes
            uint32_t a[4][4], b0[4], b1[4];
            #pragma unroll
            for (int mi = 0; mi < 4; mi++)
                ldm_x4(a[mi][0], a[mi][1], a[mi][2], a[mi][3], stA + aOff[mi] + kb);
            ldm_x4(b0[0], b0[1], b0[2], b0[3], stB + bOff + kb);
            ldm_x4(b1[0], b1[1], b1[2], b1[3], stB + bOff + kb + 16);
            #pragma unroll
            for (int mi = 0; mi < 4; mi++)
                #pragma unroll
                for (int ni = 0; ni < 4; ni++)
                    mma_f16(acc[mi][ni], a[mi][0], a[mi][1], a[mi][2], a[mi][3],
                            b0[ni], b1[ni]);
        }
    }
    #undef GISSUE

    #pragma unroll
    for (int mi = 0; mi < 4; mi++) {
        const int r0 = m0 + wm * 64 + mi * 16 + frow;
        #pragma unroll
        for (int ni = 0; ni < 4; ni++) {
            const int col = n0 + wn * 32 + ni * 8 + 2 * t4;
            const float b0 = bias[col], b1 = bias[col + 1];
            const float v00 = acc[mi][ni][0] + b0, v01 = acc[mi][ni][1] + b1;
            const float v10 = acc[mi][ni][2] + b0, v11 = acc[mi][ni][3] + b1;
            if (outHalf) {
                __half2 h0 = __floats2half2_rn(v00, v01);
                __half2 h1 = __floats2half2_rn(v10, v11);
                *(__half2*)(Ch + (size_t)r0 * N + col) = h0;
                *(__half2*)(Ch + (size_t)(r0 + 8) * N + col) = h1;
            } else {
                *(float2*)(Cf + (size_t)r0 * N + col) = make_float2(v00, v01);
                *(float2*)(Cf + (size_t)(r0 + 8) * N + col) = make_float2(v10, v11);
            }
        }
    }
}

// =================================================================
// fp16 tensor-core flash attention, ldmatrix + double-buffered K/V.
// Block = (b, h, 128 q-rows), 8 warps x 16 q-rows, full 128-key width.
// =================================================================
#define AQ 72      // Q/K pitch (halfs): 144 B
#define AV 136     // Vt/P pitch (halfs): 272 B
#define KT_HALFS (128 * AQ)   // 9216
#define VT_HALFS (64 * AV)    // 8704
#define SQ 0
#define SK0 (SQ + 128 * AQ)                 // 9216
#define SV0 (SK0 + 2 * KT_HALFS)            // 27648
#define SP  (SV0 + 2 * VT_HALFS)            // 45056
#define ATTN_HALFS (SP + 128 * AV)          // 62464
#define ATTN_SMEM_BYTES (ATTN_HALFS * 2)    // 124928 B

__global__ __launch_bounds__(256, 1) void attn_h_kernel(
    const __half* __restrict__ q, const __half* __restrict__ k,
    const __half* __restrict__ vt, __half* __restrict__ ctx)
{
    extern __shared__ __align__(16) __half hsm[];

    const int tid  = threadIdx.x;
    const int wid  = tid >> 5;
    const int lane = tid & 31;
    const int frow = lane >> 2;
    const int t4   = lane & 3;
    const int qt = blockIdx.x;
    const int h  = blockIdx.y;
    const int b  = blockIdx.z;
    const int kvh = h >> 2;

    const int qrow0 = b * SEQ + qt * 128;
    const __half* qbase = q + (size_t)qrow0 * D_MODEL + h * HD;
    const __half* kbase = k + (size_t)b * SEQ * KV_DIM + kvh * HD;
    const __half* vtbase = vt + (size_t)(b * KV_DIM + kvh * HD) * SEQ;

    const uint32_t smb = smem_u32(hsm);
    const int srow = tid >> 1;          // 0..127
    const int sc   = (tid & 1) * 32;    // halfs
    const int vrow = tid >> 2;          // 0..63
    const int vc   = (tid & 3) * 32;    // halfs

    // ---- stage Q (group 0) ----
    {
        const __half* g = qbase + (size_t)srow * D_MODEL + sc;
        uint32_t d = smb + (SQ + srow * AQ + sc) * 2;
        #pragma unroll
        for (int c = 0; c < 4; c++)
            asm volatile("cp.async.cg.shared.global [%0], [%1], 16;"
                         :: "r"(d + c * 16), "l"(g + c * 8) : "memory");
        asm volatile("cp.async.commit_group;" ::: "memory");
    }

    #define STAGE_KV(kt, buf) do {                                             \
        const __half* gk = kbase + (size_t)((kt) * 128 + srow) * KV_DIM + sc;  \
        uint32_t dk = smb + (SK0 + (buf) * KT_HALFS + srow * AQ + sc) * 2;     \
        _Pragma("unroll")                                                      \
        for (int c = 0; c < 4; c++)                                            \
            asm volatile("cp.async.cg.shared.global [%0], [%1], 16;"           \
                         :: "r"(dk + c * 16), "l"(gk + c * 8) : "memory");     \
        const __half* gv = vtbase + (size_t)vrow * SEQ + (kt) * 128 + vc;      \
        uint32_t dv = smb + (SV0 + (buf) * VT_HALFS + vrow * AV + vc) * 2;     \
        _Pragma("unroll")                                                      \
        for (int c = 0; c < 4; c++)                                            \
            asm volatile("cp.async.cg.shared.global [%0], [%1], 16;"           \
                         :: "r"(dv + c * 16), "l"(gv + c * 8) : "memory");     \
    } while (0)

    STAGE_KV(0, 0);
    asm volatile("cp.async.commit_group;" ::: "memory");

    // ldmatrix lane offsets (bytes, relative to region bases)
    const uint32_t qOff = ((wid * 16 + (lane & 15)) * AQ + (lane >> 4) * 8) * 2;
    const uint32_t pOff = ((wid * 16 + (lane & 15)) * AV + (lane >> 4) * 8) * 2;
    uint32_t kOff[4], vOff[2];
    #pragma unroll
    for (int gg = 0; gg < 4; gg++)
        kOff[gg] = (((4 * gg + (lane >> 3)) * 8 + (lane & 7)) * AQ) * 2;
    #pragma unroll
    for (int gg = 0; gg < 2; gg++)
        vOff[gg] = (((4 * gg + (lane >> 3)) * 8 + (lane & 7)) * AV) * 2;

    float mrow[2] = {-1e30f, -1e30f};
    float lrow[2] = {0.f, 0.f};
    float accO[8][4];
    #pragma unroll
    for (int ni = 0; ni < 8; ni++)
        #pragma unroll
        for (int r = 0; r < 4; r++) accO[ni][r] = 0.f;

    for (int kt = 0; kt < SEQ / 128; kt++) {
        __syncthreads();   // all warps done reading the buffer about to be overwritten
        if (kt + 1 < SEQ / 128) STAGE_KV(kt + 1, (kt + 1) & 1);
        asm volatile("cp.async.commit_group;" ::: "memory");
        asm volatile("cp.async.wait_group 1;" ::: "memory");
        __syncthreads();   // kt's K/V visible to all warps

        const uint32_t kBase = smb + (SK0 + (kt & 1) * KT_HALFS) * 2;
        const uint32_t vBase = smb + (SV0 + (kt & 1) * VT_HALFS) * 2;
        const uint32_t qBase = smb + SQ * 2;
        const uint32_t pBase = smb + SP * 2;

        // ---- S = Q @ K^T (16 q-rows x 128 keys, K = 64 = 4 k16 steps) ----
        float accS[16][4];
        #pragma unroll
        for (int ni = 0; ni < 16; ni++)
            #pragma unroll
            for (int r = 0; r < 4; r++) accS[ni][r] = 0.f;

        #pragma unroll
        for (int ks = 0; ks < 4; ks++) {
            const uint32_t kb = ks * 32;
            uint32_t a0, a1, a2, a3;
            ldm_x4(a0, a1, a2, a3, qBase + qOff + kb);
            #pragma unroll
            for (int gg = 0; gg < 4; gg++) {
                uint32_t b0[4], b1[4];
                ldm_x4(b0[0], b0[1], b0[2], b0[3], kBase + kOff[gg] + kb);
                ldm_x4(b1[0], b1[1], b1[2], b1[3], kBase + kOff[gg] + kb + 16);
                #pragma unroll
                for (int j = 0; j < 4; j++)
                    mma_f16(accS[4 * gg + j], a0, a1, a2, a3, b0[j], b1[j]);
            }
        }

        // ---- streaming softmax (rows frow, frow+8 of this warp) ----
        float mx0 = -1e30f, mx1 = -1e30f;
        #pragma unroll
        for (int ni = 0; ni < 16; ni++) {
            #pragma unroll
            for (int r = 0; r < 4; r++) accS[ni][r] *= 0.125f;
            mx0 = fmaxf(mx0, fmaxf(accS[ni][0], accS[ni][1]));
            mx1 = fmaxf(mx1, fmaxf(accS[ni][2], accS[ni][3]));
        }
        mx0 = fmaxf(mx0, __shfl_xor_sync(0xffffffffu, mx0, 1));
        mx0 = fmaxf(mx0, __shfl_xor_sync(0xffffffffu, mx0, 2));
        mx1 = fmaxf(mx1, __shfl_xor_sync(0xffffffffu, mx1, 1));
        mx1 = fmaxf(mx1, __shfl_xor_sync(0xffffffffu, mx1, 2));

        const float mn0 = fmaxf(mrow[0], mx0);
        const float mn1 = fmaxf(mrow[1], mx1);
        const float corr0 = __expf(mrow[0] - mn0);
        const float corr1 = __expf(mrow[1] - mn1);
        mrow[0] = mn0; mrow[1] = mn1;

        __half* Pw = hsm + SP + (wid * 16) * AV;
        float sum0 = 0.f, sum1 = 0.f;
        #pragma unroll
        for (int ni = 0; ni < 16; ni++) {
            float p0 = __expf(accS[ni][0] - mn0);
            float p1 = __expf(accS[ni][1] - mn0);
            float p2 = __expf(accS[ni][2] - mn1);
            float p3 = __expf(accS[ni][3] - mn1);
            sum0 += p0 + p1;
            sum1 += p2 + p3;
            const int col = ni * 8 + 2 * t4;
            *(__half2*)(Pw + frow * AV + col)       = __floats2half2_rn(p0, p1);
            *(__half2*)(Pw + (frow + 8) * AV + col) = __floats2half2_rn(p2, p3);
        }
        sum0 += __shfl_xor_sync(0xffffffffu, sum0, 1);
        sum0 += __shfl_xor_sync(0xffffffffu, sum0, 2);
        sum1 += __shfl_xor_sync(0xffffffffu, sum1, 1);
        sum1 += __shfl_xor_sync(0xffffffffu, sum1, 2);
        lrow[0] = lrow[0] * corr0 + sum0;
        lrow[1] = lrow[1] * corr1 + sum1;

        #pragma unroll
        for (int ni = 0; ni < 8; ni++) {
            accO[ni][0] *= corr0; accO[ni][1] *= corr0;
            accO[ni][2] *= corr1; accO[ni][3] *= corr1;
        }
        __syncwarp();

        // ---- O += P @ V (16 rows x 64 d, K = 128 keys = 8 k16 steps) ----
        #pragma unroll
        for (int ks = 0; ks < 8; ks++) {
            const uint32_t kb = ks * 32;
            uint32_t a0, a1, a2, a3;
            ldm_x4(a0, a1, a2, a3, pBase + pOff + kb);
            #pragma unroll
            for (int gg = 0; gg < 2; gg++) {
                uint32_t b0[4], b1[4];
                ldm_x4(b0[0], b0[1], b0[2], b0[3], vBase + vOff[gg] + kb);
                ldm_x4(b1[0], b1[1], b1[2], b1[3], vBase + vOff[gg] + kb + 16);
                #pragma unroll
                for (int j = 0; j < 4; j++)
                    mma_f16(accO[4 * gg + j], a0, a1, a2, a3, b0[j], b1[j]);
            }
        }
    }
    #undef STAGE_KV

    // ---- epilogue: ctx in fp16, [B*S][D_MODEL] ----
    const float inv0 = 1.0f / lrow[0];
    const float inv1 = 1.0f / lrow[1];
    const int r0 = qrow0 + wid * 16 + frow;
    #pragma unroll
    for (int ni = 0; ni < 8; ni++) {
        const int col = h * HD + ni * 8 + 2 * t4;
        *(__half2*)(ctx + (size_t)r0 * D_MODEL + col) =
            __floats2half2_rn(accO[ni][0] * inv0, accO[ni][1] * inv0);
        *(__half2*)(ctx + (size_t)(r0 + 8) * D_MODEL + col) =
            __floats2half2_rn(accO[ni][2] * inv1, accO[ni][3] * inv1);
    }
}

// =================================================================
extern "C" void kernel_launch(void* const* d_in, const int* in_sizes, int n_in,
                              void* d_out, int out_size)
{
    const float* x  = (const float*)d_in[0];
    const float* Wq = (const float*)d_in[1];
    const float* bq = (const float*)d_in[2];
    const float* Wk = (const float*)d_in[3];
    const float* bk = (const float*)d_in[4];
    const float* Wv = (const float*)d_in[5];
    const float* bv = (const float*)d_in[6];
    const float* Wo = (const float*)d_in[7];
    const float* bo = (const float*)d_in[8];
    float* out = (float*)d_out;

    __half *qh, *kh, *vh, *vtg, *ch, *xh, *wth;
    cudaGetSymbolAddress((void**)&qh,  g_qh);
    cudaGetSymbolAddress((void**)&kh,  g_kh);
    cudaGetSymbolAddress((void**)&vh,  g_vh);
    cudaGetSymbolAddress((void**)&vtg, g_vt);
    cudaGetSymbolAddress((void**)&ch,  g_ch);
    cudaGetSymbolAddress((void**)&xh,  g_xh);
    cudaGetSymbolAddress((void**)&wth, g_wth);

    cudaFuncSetAttribute(attn_h_kernel,
                         cudaFuncAttributeMaxDynamicSharedMemorySize, ATTN_SMEM_BYTES);
    cudaFuncSetAttribute(gemm_h_kernel,
                         cudaFuncAttributeMaxDynamicSharedMemorySize, GEMM_SMEM);

    {
        int n4 = MTOT * D_MODEL / 4;
        to_half_kernel<<<(n4 + 255) / 256, 256>>>((const float4*)x, (uint2*)xh, n4);
    }

    dim3 tb(32, 8);

    // Q projection
    transpose_half_kernel<<<dim3(D_MODEL / 32, D_MODEL / 32), tb>>>(Wq, wth, D_MODEL, D_MODEL);
    gemm_h_kernel<<<dim3(D_MODEL / 128, MTOT / 128), 256, GEMM_SMEM>>>(
        xh, wth, bq, nullptr, qh, MTOT, D_MODEL, D_MODEL, 1);
    // K projection
    transpose_half_kernel<<<dim3(KV_DIM / 32, D_MODEL / 32), tb>>>(Wk, wth, D_MODEL, KV_DIM);
    gemm_h_kernel<<<dim3(KV_DIM / 128, MTOT / 128), 256, GEMM_SMEM>>>(
        xh, wth, bk, nullptr, kh, MTOT, KV_DIM, D_MODEL, 1);
    // V projection
    transpose_half_kernel<<<dim3(KV_DIM / 32, D_MODEL / 32), tb>>>(Wv, wth, D_MODEL, KV_DIM);
    gemm_h_kernel<<<dim3(KV_DIM / 128, MTOT / 128), 256, GEMM_SMEM>>>(
        xh, wth, bv, nullptr, vh, MTOT, KV_DIM, D_MODEL, 1);

    // V transpose for fp16 B-fragments
    vtrans_kernel<<<dim3(SEQ / 32, KV_DIM / 32, BATCH), tb>>>(vh, vtg);

    // attention
    attn_h_kernel<<<dim3(SEQ / 128, NHEADS, BATCH), 256, ATTN_SMEM_BYTES>>>(qh, kh, vtg, ch);

    // output projection (fp32 out)
    transpose_half_kernel<<<dim3(D_MODEL / 32, D_MODEL / 32), tb>>>(Wo, wth, D_MODEL, D_MODEL);
    gemm_h_kernel<<<dim3(D_MODEL / 128, MTOT / 128), 256, GEMM_SMEM>>>(
        ch, wth, bo, out, nullptr, MTOT, D_MODEL, D_MODEL, 0);
}